// round 1
// baseline (speedup 1.0000x reference)
#include <cuda_runtime.h>
#include <math.h>

// Problem shape (fixed by the reference)
#define NSAMP 2048
#define OBS   48
// Layers: (out, in)
// L0: 512 x 48   L1: 256 x 512   L2: 128 x 256   L3: 12 x 128

#define THREADS 256

__device__ __forceinline__ float warp_group_reduce(float s, int G) {
    // G is 16 or 32; groups are aligned inside a warp.
    #pragma unroll
    for (int o = 16; o >= 1; o >>= 1) {
        if (o < G || G == 32) {
            if (o <= G / 2) s += __shfl_xor_sync(0xffffffffu, s, o);
        }
    }
    return s;
}

template <int OUT, int IN, int G, bool ACT>
__device__ __forceinline__ void layer(const float* __restrict__ W,
                                      const float* __restrict__ b,
                                      const float* __restrict__ x,
                                      float* __restrict__ y) {
    constexpr int NV = IN / 4;          // float4 per row
    constexpr int NG = THREADS / G;     // groups per block
    const int gid = threadIdx.x / G;
    const int gl  = threadIdx.x % G;
    const float4* __restrict__ xv = reinterpret_cast<const float4*>(x);

    for (int row = gid; row < OUT; row += NG) {
        const float4* __restrict__ Wr =
            reinterpret_cast<const float4*>(W + (size_t)row * IN);
        float s = 0.0f;
        #pragma unroll
        for (int j = gl; j < NV; j += G) {
            float4 w = Wr[j];
            float4 v = xv[j];
            s = fmaf(w.x, v.x, s);
            s = fmaf(w.y, v.y, s);
            s = fmaf(w.z, v.z, s);
            s = fmaf(w.w, v.w, s);
        }
        // reduce across the G lanes of this group (aligned within warp)
        #pragma unroll
        for (int o = G / 2; o >= 1; o >>= 1)
            s += __shfl_xor_sync(0xffffffffu, s, o);
        if (gl == 0) {
            s += b[row];
            if (ACT)
                s = (s > 0.0f) ? s : (__expf(s) - 1.0f);  // ELU(alpha=1)
            y[row] = s;
        }
    }
}

__global__ void __launch_bounds__(THREADS, 8)
batched_teacher_policy_kernel(const float* __restrict__ obs,
                              const float* __restrict__ mean,
                              const float* __restrict__ stdv,
                              const float* __restrict__ W0,
                              const float* __restrict__ b0,
                              const float* __restrict__ W1,
                              const float* __restrict__ b1,
                              const float* __restrict__ W2,
                              const float* __restrict__ b2,
                              const float* __restrict__ W3,
                              const float* __restrict__ b3,
                              float* __restrict__ out) {
    const int n = blockIdx.x;
    const int tid = threadIdx.x;

    __shared__ __align__(16) float bufA[512];
    __shared__ __align__(16) float bufB[512];

    // x0 = clip((obs-mean)/std, -5, 5)
    if (tid < OBS) {
        const int i = n * OBS + tid;
        float v = (obs[i] - mean[i]) / stdv[i];
        bufA[tid] = fminf(fmaxf(v, -5.0f), 5.0f);
    }
    __syncthreads();

    // L0: 512 x 48, half-warp (16 lanes) per row since only 12 float4/row
    layer<512, 48, 16, true>(W0 + (size_t)n * 512 * 48, b0 + (size_t)n * 512,
                             bufA, bufB);
    __syncthreads();

    // L1: 256 x 512, full warp per row (128 float4/row -> 4 per lane)
    layer<256, 512, 32, true>(W1 + (size_t)n * 256 * 512, b1 + (size_t)n * 256,
                              bufB, bufA);
    __syncthreads();

    // L2: 128 x 256
    layer<128, 256, 32, true>(W2 + (size_t)n * 128 * 256, b2 + (size_t)n * 128,
                              bufA, bufB);
    __syncthreads();

    // L3: 12 x 128, no ELU
    layer<12, 128, 32, false>(W3 + (size_t)n * 12 * 128, b3 + (size_t)n * 12,
                              bufB, bufA);
    __syncthreads();

    if (tid < 12)
        out[n * 12 + tid] = tanhf(bufA[tid]);
}

extern "C" void kernel_launch(void* const* d_in, const int* in_sizes, int n_in,
                              void* d_out, int out_size) {
    const float* obs  = (const float*)d_in[0];
    const float* mean = (const float*)d_in[1];
    const float* stdv = (const float*)d_in[2];
    const float* W0   = (const float*)d_in[3];
    const float* b0   = (const float*)d_in[4];
    const float* W1   = (const float*)d_in[5];
    const float* b1   = (const float*)d_in[6];
    const float* W2   = (const float*)d_in[7];
    const float* b2   = (const float*)d_in[8];
    const float* W3   = (const float*)d_in[9];
    const float* b3   = (const float*)d_in[10];
    float* out = (float*)d_out;

    batched_teacher_policy_kernel<<<NSAMP, THREADS>>>(
        obs, mean, stdv, W0, b0, W1, b1, W2, b2, W3, b3, out);
}

// round 2
// speedup vs baseline: 1.1825x; 1.1825x over previous
#include <cuda_runtime.h>
#include <math.h>

// Problem shape (fixed by the reference)
#define NSAMP 2048
#define OBS   48
// Layers: (out, in)
// L0: 512 x 48   L1: 256 x 512   L2: 128 x 256   L3: 12 x 128

#define THREADS 256

__device__ __forceinline__ float elu(float s) {
    return (s > 0.0f) ? s : (__expf(s) - 1.0f);
}

// Two rows per group per iteration: 8 independent weight loads in flight
// before any dependent FMA/reduce. Requires OUT % (2 * THREADS/G) == 0.
template <int OUT, int IN, int G, bool ACT>
__device__ __forceinline__ void layer2(const float* __restrict__ W,
                                       const float* __restrict__ b,
                                       const float* __restrict__ x,
                                       float* __restrict__ y) {
    constexpr int NV = IN / 4;          // float4 per row
    constexpr int NG = THREADS / G;     // groups per block
    const int gid = threadIdx.x / G;
    const int gl  = threadIdx.x % G;
    const float4* __restrict__ xv = reinterpret_cast<const float4*>(x);

    #pragma unroll
    for (int row = gid; row < OUT; row += 2 * NG) {
        const int row1 = row + NG;
        const float4* __restrict__ Wr0 =
            reinterpret_cast<const float4*>(W + (size_t)row  * IN);
        const float4* __restrict__ Wr1 =
            reinterpret_cast<const float4*>(W + (size_t)row1 * IN);
        float s0 = 0.0f, s1 = 0.0f;
        #pragma unroll
        for (int j = gl; j < NV; j += G) {
            float4 w0 = __ldcs(Wr0 + j);
            float4 w1 = __ldcs(Wr1 + j);
            float4 v  = xv[j];
            s0 = fmaf(w0.x, v.x, s0);
            s0 = fmaf(w0.y, v.y, s0);
            s0 = fmaf(w0.z, v.z, s0);
            s0 = fmaf(w0.w, v.w, s0);
            s1 = fmaf(w1.x, v.x, s1);
            s1 = fmaf(w1.y, v.y, s1);
            s1 = fmaf(w1.z, v.z, s1);
            s1 = fmaf(w1.w, v.w, s1);
        }
        #pragma unroll
        for (int o = G / 2; o >= 1; o >>= 1) {
            s0 += __shfl_xor_sync(0xffffffffu, s0, o);
            s1 += __shfl_xor_sync(0xffffffffu, s1, o);
        }
        if (gl == 0) {
            s0 += b[row];
            s1 += b[row1];
            if (ACT) { s0 = elu(s0); s1 = elu(s1); }
            y[row]  = s0;
            y[row1] = s1;
        }
    }
}

// Single-row variant for the tiny final layer.
template <int OUT, int IN, int G, bool ACT>
__device__ __forceinline__ void layer1(const float* __restrict__ W,
                                       const float* __restrict__ b,
                                       const float* __restrict__ x,
                                       float* __restrict__ y) {
    constexpr int NV = IN / 4;
    constexpr int NG = THREADS / G;
    const int gid = threadIdx.x / G;
    const int gl  = threadIdx.x % G;
    const float4* __restrict__ xv = reinterpret_cast<const float4*>(x);

    for (int row = gid; row < OUT; row += NG) {
        const float4* __restrict__ Wr =
            reinterpret_cast<const float4*>(W + (size_t)row * IN);
        float s = 0.0f;
        #pragma unroll
        for (int j = gl; j < NV; j += G) {
            float4 w = __ldcs(Wr + j);
            float4 v = xv[j];
            s = fmaf(w.x, v.x, s);
            s = fmaf(w.y, v.y, s);
            s = fmaf(w.z, v.z, s);
            s = fmaf(w.w, v.w, s);
        }
        #pragma unroll
        for (int o = G / 2; o >= 1; o >>= 1)
            s += __shfl_xor_sync(0xffffffffu, s, o);
        if (gl == 0) {
            s += b[row];
            if (ACT) s = elu(s);
            y[row] = s;
        }
    }
}

__global__ void __launch_bounds__(THREADS, 8)
batched_teacher_policy_kernel(const float* __restrict__ obs,
                              const float* __restrict__ mean,
                              const float* __restrict__ stdv,
                              const float* __restrict__ W0,
                              const float* __restrict__ b0,
                              const float* __restrict__ W1,
                              const float* __restrict__ b1,
                              const float* __restrict__ W2,
                              const float* __restrict__ b2,
                              const float* __restrict__ W3,
                              const float* __restrict__ b3,
                              float* __restrict__ out) {
    const int n = blockIdx.x;
    const int tid = threadIdx.x;

    __shared__ __align__(16) float bufA[512];
    __shared__ __align__(16) float bufB[512];

    // x0 = clip((obs-mean)/std, -5, 5)
    if (tid < OBS) {
        const int i = n * OBS + tid;
        float v = (obs[i] - mean[i]) / stdv[i];
        bufA[tid] = fminf(fmaxf(v, -5.0f), 5.0f);
    }
    __syncthreads();

    // L0: 512 x 48, 16 lanes per row (12 float4/row)
    layer2<512, 48, 16, true>(W0 + (size_t)n * 512 * 48, b0 + (size_t)n * 512,
                              bufA, bufB);
    __syncthreads();

    // L1: 256 x 512
    layer2<256, 512, 32, true>(W1 + (size_t)n * 256 * 512, b1 + (size_t)n * 256,
                               bufB, bufA);
    __syncthreads();

    // L2: 128 x 256
    layer2<128, 256, 32, true>(W2 + (size_t)n * 128 * 256, b2 + (size_t)n * 128,
                               bufA, bufB);
    __syncthreads();

    // L3: 12 x 128, no ELU
    layer1<12, 128, 32, false>(W3 + (size_t)n * 12 * 128, b3 + (size_t)n * 12,
                               bufB, bufA);
    __syncthreads();

    if (tid < 12)
        out[n * 12 + tid] = tanhf(bufA[tid]);
}

extern "C" void kernel_launch(void* const* d_in, const int* in_sizes, int n_in,
                              void* d_out, int out_size) {
    const float* obs  = (const float*)d_in[0];
    const float* mean = (const float*)d_in[1];
    const float* stdv = (const float*)d_in[2];
    const float* W0   = (const float*)d_in[3];
    const float* b0   = (const float*)d_in[4];
    const float* W1   = (const float*)d_in[5];
    const float* b1   = (const float*)d_in[6];
    const float* W2   = (const float*)d_in[7];
    const float* b2   = (const float*)d_in[8];
    const float* W3   = (const float*)d_in[9];
    const float* b3   = (const float*)d_in[10];
    float* out = (float*)d_out;

    batched_teacher_policy_kernel<<<NSAMP, THREADS>>>(
        obs, mean, stdv, W0, b0, W1, b1, W2, b2, W3, b3, out);
}